// round 12
// baseline (speedup 1.0000x reference)
#include <cuda_runtime.h>
#include <cuda_bf16.h>
#include <cstdint>

// EdgeMLPMPN: out[e] = W3 @ elu(W2 @ elu(W1 @ [x[src];x[tgt]] + b1) + b2) + b3
//   Kernel 1 (split-bf16 mma.sync GEMM, proven): [A|B](n) = [W1a|W1b] @ x[n]
//   Kernel 2 (warp-specialized pipeline, TF32):
//       producers (warps 0-7): epilogue of tile i-2 (overlapped with gather LDG latency)
//                              + gather + elu + cvt.rna.tf32 refill
//       consumers (warps 8-15): single-pass m16n8k8 tf32 mma, raw acc -> same buffer
// Compiled at sm_100 (no 'a'): mma.sync only, no tcgen05.

#define C 128
#define NMAX 50000
#define ET 128
#define EDGE_GRID 148
typedef unsigned long long ull;
typedef uint32_t u32;

__device__ float g_A[(size_t)NMAX * C];
__device__ float g_B[(size_t)NMAX * C];

__device__ __forceinline__ float elu_fast(float x) {
    return x > 0.0f ? x : (__expf(x) - 1.0f);
}

__device__ __forceinline__ bool idx_is_i64(const void* p) {
    const ull* q = (const ull*)p;
    unsigned hi = 0;
    #pragma unroll
    for (int i = 0; i < 8; i++) hi |= (unsigned)(q[i] >> 32);
    return hi == 0;
}

__device__ __forceinline__ u32 smem_u32(const void* p) {
    u32 a; asm("{ .reg .u64 t; cvta.to.shared.u64 t, %1; cvt.u32.u64 %0, t; }" : "=r"(a) : "l"(p));
    return a;
}

__device__ __forceinline__ void ldsm4(u32 &r0, u32 &r1, u32 &r2, u32 &r3, u32 addr) {
    asm volatile("ldmatrix.sync.aligned.m8n8.x4.shared.b16 {%0,%1,%2,%3}, [%4];"
                 : "=r"(r0), "=r"(r1), "=r"(r2), "=r"(r3) : "r"(addr));
}

__device__ __forceinline__ void mma_bf16(float* d, u32 a0, u32 a1, u32 a2, u32 a3,
                                         u32 b0, u32 b1) {
    asm volatile("mma.sync.aligned.m16n8k16.row.col.f32.bf16.bf16.f32 "
                 "{%0,%1,%2,%3}, {%4,%5,%6,%7}, {%8,%9}, {%0,%1,%2,%3};"
                 : "+f"(d[0]), "+f"(d[1]), "+f"(d[2]), "+f"(d[3])
                 : "r"(a0), "r"(a1), "r"(a2), "r"(a3), "r"(b0), "r"(b1));
}

__device__ __forceinline__ void mma_tf32(float* d, u32 a0, u32 a1, u32 a2, u32 a3,
                                         u32 b0, u32 b1) {
    asm volatile("mma.sync.aligned.m16n8k8.row.col.f32.tf32.tf32.f32 "
                 "{%0,%1,%2,%3}, {%4,%5,%6,%7}, {%8,%9}, {%0,%1,%2,%3};"
                 : "+f"(d[0]), "+f"(d[1]), "+f"(d[2]), "+f"(d[3])
                 : "r"(a0), "r"(a1), "r"(a2), "r"(a3), "r"(b0), "r"(b1));
}

__device__ __forceinline__ u32 cvt_tf32(float f) {
    u32 r; asm("cvt.rna.tf32.f32 %0, %1;" : "=r"(r) : "f"(f));
    return r;
}

__device__ __forceinline__ u32 cvt_bf2(float lo, float hi) {
    u32 r; asm("cvt.rn.bf16x2.f32 %0, %1, %2;" : "=r"(r) : "f"(hi), "f"(lo));
    return r;
}

__device__ __forceinline__ void split4(float4 h, ull &hiP, ull &loP) {
    u32 hxy = cvt_bf2(h.x, h.y);
    u32 hzw = cvt_bf2(h.z, h.w);
    float rx = h.x - __uint_as_float(hxy << 16);
    float ry = h.y - __uint_as_float(hxy & 0xFFFF0000u);
    float rz = h.z - __uint_as_float(hzw << 16);
    float rw = h.w - __uint_as_float(hzw & 0xFFFF0000u);
    u32 lxy = cvt_bf2(rx, ry);
    u32 lzw = cvt_bf2(rz, rw);
    hiP = (ull)hxy | ((ull)hzw << 32);
    loP = (ull)lxy | ((ull)lzw << 32);
}

#define BAR_SYNC(id, n)   asm volatile("bar.sync %0, %1;"   :: "r"(id), "r"(n) : "memory")
#define BAR_ARRIVE(id, n) asm volatile("bar.arrive %0, %1;" :: "r"(id), "r"(n) : "memory")
#define MEMBAR_CTA()      asm volatile("membar.cta;" ::: "memory")

#define HSTRIDE 272

// ---------------------------------------------------------------------------
// Kernel 1: node precompute as split-bf16 MMA GEMM (unchanged, proven).
// ---------------------------------------------------------------------------
#define PC_XHI  0
#define PC_XLO  34816
#define PC_WHI  69632
#define PC_WLO  139264
#define PC_SMEM 208896

__global__ void __launch_bounds__(512, 1)
precompute_mma_kernel(const float* __restrict__ x, const float* __restrict__ W1, int N)
{
    extern __shared__ __align__(128) char smc[];
    u32 sb = smem_u32(smc);
    int tid = threadIdx.x;
    int lane = tid & 31, w = tid >> 5;
    int n0 = blockIdx.x * 128;

    const float4* W1v = (const float4*)W1;
    for (int idx = tid; idx < 256 * 32; idx += 512) {
        int j = idx >> 5, c4 = idx & 31;
        float4 v = (j < 128) ? W1v[j * 64 + c4] : W1v[(j - 128) * 64 + 32 + c4];
        ull hp, lp;
        split4(v, hp, lp);
        *(ull*)(smc + PC_WHI + j * HSTRIDE + c4 * 8) = hp;
        *(ull*)(smc + PC_WLO + j * HSTRIDE + c4 * 8) = lp;
    }
    for (int idx = tid; idx < 128 * 32; idx += 512) {
        int r = idx >> 5, c4 = idx & 31;
        int n = min(n0 + r, N - 1);
        float4 v = ((const float4*)x)[(size_t)n * 32 + c4];
        ull hp, lp;
        split4(v, hp, lp);
        *(ull*)(smc + PC_XHI + r * HSTRIDE + c4 * 8) = hp;
        *(ull*)(smc + PC_XLO + r * HSTRIDE + c4 * 8) = lp;
    }
    __syncthreads();

    int wm = w & 3, wn = w >> 2;
    int g = lane >> 3, lr = lane & 7;
    int arow = (g & 1) * 8 + lr;
    u32 kh = (u32)((g >> 1) * 16);

    u32 aBaseHi = sb + PC_XHI + (wm * 32 + arow) * HSTRIDE + kh;
    u32 aBaseLo = sb + PC_XLO + (wm * 32 + arow) * HSTRIDE + kh;
    u32 bBaseHi = sb + PC_WHI + (wn * 64 + arow) * HSTRIDE + kh;
    u32 bBaseLo = sb + PC_WLO + (wn * 64 + arow) * HSTRIDE + kh;

    float acc[2][8][4];
    #pragma unroll
    for (int mi = 0; mi < 2; mi++)
        #pragma unroll
        for (int ni = 0; ni < 8; ni++)
            #pragma unroll
            for (int q = 0; q < 4; q++) acc[mi][ni][q] = 0.0f;

    #pragma unroll
    for (int ks = 0; ks < 8; ks++) {
        u32 ko = (u32)(ks * 32);
        u32 bh[8][2], bl[8][2];
        #pragma unroll
        for (int gB = 0; gB < 4; gB++) {
            u32 r0,r1,r2,r3;
            ldsm4(r0,r1,r2,r3, bBaseHi + gB * 16 * HSTRIDE + ko);
            bh[gB*2][0]=r0; bh[gB*2][1]=r2; bh[gB*2+1][0]=r1; bh[gB*2+1][1]=r3;
        }
        #pragma unroll
        for (int gB = 0; gB < 4; gB++) {
            u32 r0,r1,r2,r3;
            ldsm4(r0,r1,r2,r3, bBaseLo + gB * 16 * HSTRIDE + ko);
            bl[gB*2][0]=r0; bl[gB*2][1]=r2; bl[gB*2+1][0]=r1; bl[gB*2+1][1]=r3;
        }
        #pragma unroll
        for (int mi = 0; mi < 2; mi++) {
            u32 a0,a1,a2,a3, c0,c1,c2,c3;
            ldsm4(a0,a1,a2,a3, aBaseHi + mi * 16 * HSTRIDE + ko);
            ldsm4(c0,c1,c2,c3, aBaseLo + mi * 16 * HSTRIDE + ko);
            #pragma unroll
            for (int ni = 0; ni < 8; ni++) {
                mma_bf16(acc[mi][ni], a0,a1,a2,a3, bh[ni][0], bh[ni][1]);
                mma_bf16(acc[mi][ni], a0,a1,a2,a3, bl[ni][0], bl[ni][1]);
                mma_bf16(acc[mi][ni], c0,c1,c2,c3, bh[ni][0], bh[ni][1]);
            }
        }
    }

    float* dst = (wn < 2) ? g_A : g_B;
    int jbase = (wn & 1) * 64;
    #pragma unroll
    for (int mi = 0; mi < 2; mi++) {
        int r0 = wm * 32 + mi * 16 + (lane >> 2);
        #pragma unroll
        for (int ni = 0; ni < 8; ni++) {
            int j = jbase + ni * 8 + (lane & 3) * 2;
            int n_a = n0 + r0, n_b = n0 + r0 + 8;
            if (n_a < N) *(float2*)&dst[(size_t)n_a * C + j] = make_float2(acc[mi][ni][0], acc[mi][ni][1]);
            if (n_b < N) *(float2*)&dst[(size_t)n_b * C + j] = make_float2(acc[mi][ni][2], acc[mi][ni][3]);
        }
    }
}

// ---------------------------------------------------------------------------
// Kernel 2: warp-specialized pipelined edge MLP, TF32, producer-side epilogue.
// H buffer doubles as acc buffer: consumer overwrites consumed H with raw acc.
// Barriers: READY(b)=1+b (prod arrive / cons sync), DONE(b)=3+b (cons arrive /
// prod sync), pair(wm)=5+wm (64 thr: A-row readers finish before acc stores).
// ---------------------------------------------------------------------------
#define WP_STRIDE 544
#define H_STRIDE  528
#define H_TILE    (ET * H_STRIDE)          // 67584
#define OFF_WP    0                        // 69632
#define OFF_H     69632                    // + 2*67584 = 204800
#define OFF_B1    204800
#define OFF_B2    205312
#define OFF_W3    205824
#define ED_SMEM   206464

#define NTILES(E) (((E) + ET - 1) / ET)

__global__ void __launch_bounds__(512, 1)
edge_kernel(const void* __restrict__ ei,
            const float* __restrict__ W2, const float* __restrict__ b1,
            const float* __restrict__ b2, const float* __restrict__ W3,
            const float* __restrict__ b3, float* __restrict__ out, int E)
{
    extern __shared__ __align__(128) char smc[];
    u32 sb = smem_u32(smc);
    float* b1s = (float*)(smc + OFF_B1);
    float* b2s = (float*)(smc + OFF_B2);
    float* w3s = (float*)(smc + OFF_W3);

    int tid = threadIdx.x;
    int lane = tid & 31, w = tid >> 5;
    bool i64 = idx_is_i64(ei);

    if (tid < 128) { b1s[tid] = b1[tid]; b2s[tid] = b2[tid]; w3s[tid] = W3[tid]; }
    // Stage W2 into paired tf32 layout (rna): slot (n, ks, q) <- (W[n][8ks+q], W[n][8ks+q+4])
    for (int idx = tid; idx < 128 * 64; idx += 512) {
        int n = idx >> 6, rest = idx & 63;
        int ks = rest >> 2, q = rest & 3;
        u32 v0 = cvt_tf32(W2[n * 128 + ks * 8 + q]);
        u32 v1 = cvt_tf32(W2[n * 128 + ks * 8 + q + 4]);
        *(ull*)(smc + OFF_WP + n * WP_STRIDE + ks * 32 + q * 8) = (ull)v0 | ((ull)v1 << 32);
    }
    __syncthreads();

    int ntiles = NTILES(E);

    if (w < 8) {
        // ========== PRODUCERS (256 thr): epilogue(i-2) + gather/refill(i) ==========
        int el0 = w * 16;                  // 16 edges per producer warp
        int r = lane >> 3;                 // edge-in-group 0..3
        int q = lane & 7;                  // float4 index within 128B line
        const float4* b1v = (const float4*)b1s;
        const float4* b2v = (const float4*)b2s;
        const float4* w3v = (const float4*)w3s;
        float b3v = b3[0];
        int i = 0;
        int t = blockIdx.x;
        for (; t < ntiles; t += EDGE_GRID, i++) {
            int b = i & 1;
            int myidx;
            {
                int ee = min(t * ET + el0 + (lane & 15), E - 1);
                if (i64) {
                    const long long* qq = (const long long*)ei;
                    myidx = (int)((lane < 16) ? qq[ee] : qq[(size_t)E + ee]);
                } else {
                    const int* qq = (const int*)ei;
                    myidx = (lane < 16) ? qq[ee] : qq[(size_t)E + ee];
                }
            }
            // Prefetch gg=0 gathers BEFORE the DONE wait + epilogue (latency overlap)
            float4 av[4], bv[4];
            {
                int s  = __shfl_sync(0xFFFFFFFFu, myidx, r);
                int tg = __shfl_sync(0xFFFFFFFFu, myidx, 16 + r);
                const float4* Ar = (const float4*)g_A + (size_t)s  * 32 + q;
                const float4* Br = (const float4*)g_B + (size_t)tg * 32 + q;
                #pragma unroll
                for (int p = 0; p < 4; p++) { av[p] = Ar[8 * p]; bv[p] = Br[8 * p]; }
            }
            if (i >= 2) {
                BAR_SYNC(3 + b, 512);          // DONE(b): acc of tile t-2G ready
                int toldBase = (t - 2 * EDGE_GRID) * ET;
                #pragma unroll
                for (int gg = 0; gg < 4; gg++) {
                    int j = gg * 4 + r;
                    const char* hh = smc + OFF_H + b * H_TILE + (el0 + j) * H_STRIDE + q * 16;
                    float s = 0.0f;
                    #pragma unroll
                    for (int p = 0; p < 4; p++) {
                        float4 a = *(const float4*)(hh + p * 128);
                        float4 c2 = b2v[q + 8 * p];
                        float4 c3 = w3v[q + 8 * p];
                        s = fmaf(c3.x, elu_fast(a.x + c2.x), s);
                        s = fmaf(c3.y, elu_fast(a.y + c2.y), s);
                        s = fmaf(c3.z, elu_fast(a.z + c2.z), s);
                        s = fmaf(c3.w, elu_fast(a.w + c2.w), s);
                    }
                    s += __shfl_xor_sync(0xFFFFFFFFu, s, 1);
                    s += __shfl_xor_sync(0xFFFFFFFFu, s, 2);
                    s += __shfl_xor_sync(0xFFFFFFFFu, s, 4);
                    if (q == 0) out[toldBase + el0 + j] = s + b3v;
                }
            }
            // Refill buffer b with tile t
            #pragma unroll
            for (int gg = 0; gg < 4; gg++) {
                float4 nav[4], nbv[4];
                if (gg < 3) {
                    int jn = (gg + 1) * 4 + r;
                    int s  = __shfl_sync(0xFFFFFFFFu, myidx, jn);
                    int tg = __shfl_sync(0xFFFFFFFFu, myidx, 16 + jn);
                    const float4* Ar = (const float4*)g_A + (size_t)s  * 32 + q;
                    const float4* Br = (const float4*)g_B + (size_t)tg * 32 + q;
                    #pragma unroll
                    for (int p = 0; p < 4; p++) { nav[p] = Ar[8 * p]; nbv[p] = Br[8 * p]; }
                }
                int j = gg * 4 + r;
                char* hh = smc + OFF_H + b * H_TILE + (el0 + j) * H_STRIDE + q * 16;
                #pragma unroll
                for (int p = 0; p < 4; p++) {
                    float4 bi = b1v[q + 8 * p];
                    uint4 hv;
                    hv.x = cvt_tf32(elu_fast(av[p].x + bv[p].x + bi.x));
                    hv.y = cvt_tf32(elu_fast(av[p].y + bv[p].y + bi.y));
                    hv.z = cvt_tf32(elu_fast(av[p].z + bv[p].z + bi.z));
                    hv.w = cvt_tf32(elu_fast(av[p].w + bv[p].w + bi.w));
                    *(uint4*)(hh + p * 128) = hv;
                }
                if (gg < 3) {
                    #pragma unroll
                    for (int p = 0; p < 4; p++) { av[p] = nav[p]; bv[p] = nbv[p]; }
                }
            }
            MEMBAR_CTA();
            BAR_ARRIVE(1 + b, 512);            // READY(b)
        }
        // Drain: epilogue for the last two tiles (still in buffers)
        #pragma unroll 1
        for (int kk = 0; kk < 2; kk++, i++) {
            int b = i & 1;
            int t_old = t - (2 - kk) * EDGE_GRID;
            if (t_old < 0) continue;
            BAR_SYNC(3 + b, 512);
            int toldBase = t_old * ET;
            #pragma unroll
            for (int gg = 0; gg < 4; gg++) {
                int j = gg * 4 + r;
                const char* hh = smc + OFF_H + b * H_TILE + (el0 + j) * H_STRIDE + q * 16;
                float s = 0.0f;
                #pragma unroll
                for (int p = 0; p < 4; p++) {
                    float4 a = *(const float4*)(hh + p * 128);
                    float4 c2 = b2v[q + 8 * p];
                    float4 c3 = w3v[q + 8 * p];
                    s = fmaf(c3.x, elu_fast(a.x + c2.x), s);
                    s = fmaf(c3.y, elu_fast(a.y + c2.y), s);
                    s = fmaf(c3.z, elu_fast(a.z + c2.z), s);
                    s = fmaf(c3.w, elu_fast(a.w + c2.w), s);
                }
                s += __shfl_xor_sync(0xFFFFFFFFu, s, 1);
                s += __shfl_xor_sync(0xFFFFFFFFu, s, 2);
                s += __shfl_xor_sync(0xFFFFFFFFu, s, 4);
                if (q == 0) out[toldBase + el0 + j] = s + b3v;
            }
        }
    } else {
        // ========== CONSUMERS (256 thr): tf32 MMA, raw acc -> buffer ==========
        int cw = w - 8;
        int wm = cw & 3;                  // row block [wm*32,+32)
        int wh = cw >> 2;                 // col half  [wh*64,+64)
        int lg = lane >> 2;               // group id 0..7
        int lq = lane & 3;                // thread-in-group

        u32 bBase = sb + OFF_WP + (wh * 64 + lg) * WP_STRIDE + lq * 8;

        int i = 0;
        for (int t = blockIdx.x; t < ntiles; t += EDGE_GRID, i++) {
            int b = i & 1;

            float acc[2][8][4];
            #pragma unroll
            for (int mi = 0; mi < 2; mi++)
                #pragma unroll
                for (int ni = 0; ni < 8; ni++)
                    #pragma unroll
                    for (int qq = 0; qq < 4; qq++) acc[mi][ni][qq] = 0.0f;

            u32 aBase = sb + OFF_H + b * H_TILE + (wm * 32 + lg) * H_STRIDE + lq * 4;

            BAR_SYNC(1 + b, 512);              // READY(b)

            #pragma unroll
            for (int ks = 0; ks < 16; ks++) {
                u32 ko = (u32)(ks * 32);
                u32 bb[8][2];
                #pragma unroll
                for (int ni = 0; ni < 8; ni++) {
                    ull v = *(const ull*)(smc + (bBase - sb) + ni * 8 * WP_STRIDE + ko);
                    bb[ni][0] = (u32)v; bb[ni][1] = (u32)(v >> 32);
                }
                #pragma unroll
                for (int mi = 0; mi < 2; mi++) {
                    u32 ab = aBase - sb + mi * 16 * H_STRIDE + ko;
                    u32 a0 = *(const u32*)(smc + ab);
                    u32 a2 = *(const u32*)(smc + ab + 16);
                    u32 a1 = *(const u32*)(smc + ab + 8 * H_STRIDE);
                    u32 a3 = *(const u32*)(smc + ab + 8 * H_STRIDE + 16);
                    #pragma unroll
                    for (int ni = 0; ni < 8; ni++)
                        mma_tf32(acc[mi][ni], a0, a1, a2, a3, bb[ni][0], bb[ni][1]);
                }
            }

            // Both wh-warps of this wm must finish reading A rows before overwrite
            BAR_SYNC(5 + wm, 64);

            // Write raw acc into buffer b: row -> H row, col j -> word j
            #pragma unroll
            for (int mi = 0; mi < 2; mi++) {
                char* rowA = smc + OFF_H + b * H_TILE + (wm * 32 + mi * 16 + lg) * H_STRIDE;
                char* rowB = rowA + 8 * H_STRIDE;
                #pragma unroll
                for (int ni = 0; ni < 8; ni++) {
                    int j = wh * 64 + ni * 8 + lq * 2;
                    *(float2*)(rowA + j * 4) = make_float2(acc[mi][ni][0], acc[mi][ni][1]);
                    *(float2*)(rowB + j * 4) = make_float2(acc[mi][ni][2], acc[mi][ni][3]);
                }
            }
            MEMBAR_CTA();
            BAR_ARRIVE(3 + b, 512);            // DONE(b)
        }
    }
}

// ---------------------------------------------------------------------------
extern "C" void kernel_launch(void* const* d_in, const int* in_sizes, int n_in,
                              void* d_out, int out_size)
{
    const float* x  = (const float*)d_in[0];
    const void*  ei = d_in[1];
    const float* W1 = (const float*)d_in[2];
    const float* b1 = (const float*)d_in[3];
    const float* W2 = (const float*)d_in[4];
    const float* b2 = (const float*)d_in[5];
    const float* W3 = (const float*)d_in[6];
    const float* b3 = (const float*)d_in[7];
    float* out = (float*)d_out;

    int N = in_sizes[0] / C;        // 50000
    int E = in_sizes[1] / 2;        // 640000

    cudaFuncSetAttribute(precompute_mma_kernel, cudaFuncAttributeMaxDynamicSharedMemorySize, PC_SMEM);
    cudaFuncSetAttribute(edge_kernel,           cudaFuncAttributeMaxDynamicSharedMemorySize, ED_SMEM);

    precompute_mma_kernel<<<(N + 127) / 128, 512, PC_SMEM>>>(x, W1, N);
    edge_kernel<<<EDGE_GRID, 512, ED_SMEM>>>(ei, W2, b1, b2, W3, b3, out, E);
}

// round 13
// speedup vs baseline: 1.3294x; 1.3294x over previous
#include <cuda_runtime.h>
#include <cuda_bf16.h>
#include <cstdint>

// EdgeMLPMPN: out[e] = W3 @ elu(W2 @ elu(W1 @ [x[src];x[tgt]] + b1) + b2) + b3
//   Kernel 1 (tf32 single-pass mma.sync GEMM): [A|B](n) = [W1a|W1b] @ x[n]
//   Kernel 2 (round-10 proven): warp-specialized pipeline, TF32 single-pass,
//       producers: prefetch-pipelined gather + elu + cvt.rna.tf32
//       consumers: m16n8k8 tf32 mma + pairwise epilogue
// Compiled at sm_100 (no 'a'): mma.sync only, no tcgen05.

#define C 128
#define NMAX 50000
#define ET 128
#define NBUF 2
#define EDGE_GRID 148
typedef unsigned long long ull;
typedef uint32_t u32;

__device__ float g_A[(size_t)NMAX * C];
__device__ float g_B[(size_t)NMAX * C];

__device__ __forceinline__ float elu_fast(float x) {
    return x > 0.0f ? x : (__expf(x) - 1.0f);
}

__device__ __forceinline__ bool idx_is_i64(const void* p) {
    const ull* q = (const ull*)p;
    unsigned hi = 0;
    #pragma unroll
    for (int i = 0; i < 8; i++) hi |= (unsigned)(q[i] >> 32);
    return hi == 0;
}

__device__ __forceinline__ u32 smem_u32(const void* p) {
    u32 a; asm("{ .reg .u64 t; cvta.to.shared.u64 t, %1; cvt.u32.u64 %0, t; }" : "=r"(a) : "l"(p));
    return a;
}

__device__ __forceinline__ void mma_tf32(float* d, u32 a0, u32 a1, u32 a2, u32 a3,
                                         u32 b0, u32 b1) {
    asm volatile("mma.sync.aligned.m16n8k8.row.col.f32.tf32.tf32.f32 "
                 "{%0,%1,%2,%3}, {%4,%5,%6,%7}, {%8,%9}, {%0,%1,%2,%3};"
                 : "+f"(d[0]), "+f"(d[1]), "+f"(d[2]), "+f"(d[3])
                 : "r"(a0), "r"(a1), "r"(a2), "r"(a3), "r"(b0), "r"(b1));
}

__device__ __forceinline__ u32 cvt_tf32(float f) {
    u32 r; asm("cvt.rna.tf32.f32 %0, %1;" : "=r"(r) : "f"(f));
    return r;
}

#define BAR_SYNC(id, n)   asm volatile("bar.sync %0, %1;"   :: "r"(id), "r"(n) : "memory")
#define BAR_ARRIVE(id, n) asm volatile("bar.arrive %0, %1;" :: "r"(id), "r"(n) : "memory")
#define MEMBAR_CTA()      asm volatile("membar.cta;" ::: "memory")

#define WP_STRIDE 544
#define H_STRIDE  528

// ---------------------------------------------------------------------------
// Kernel 1: node precompute, tf32 single-pass MMA GEMM.
// Out[128 nodes x 256 ch] = X[128x128] @ W1eff[256x128]^T
//   W1eff[n][k] = (n<128) ? W1[n][k] : W1[n-128][128+k]
// smem: X in H-layout [128][528B], W1 in WP-paired layout [256][544B]
// Warp (wm,wn): rows [wm*32,+32), cols [wn*64,+64); consumer-identical loop.
// ---------------------------------------------------------------------------
#define PC_X    0
#define PC_WP   67584
#define PC_SMEM (67584 + 256 * WP_STRIDE)    // 206848

__global__ void __launch_bounds__(512, 1)
precompute_mma_kernel(const float* __restrict__ x, const float* __restrict__ W1, int N)
{
    extern __shared__ __align__(128) char smc[];
    u32 sb = smem_u32(smc);
    int tid = threadIdx.x;
    int lane = tid & 31, w = tid >> 5;
    int n0 = blockIdx.x * 128;

    // Stage W1eff into WP-paired tf32 layout: slot (n,ks,q) <- (W1eff[n][8ks+q], W1eff[n][8ks+q+4])
    for (int idx = tid; idx < 256 * 64; idx += 512) {
        int n = idx >> 6, rest = idx & 63;
        int ks = rest >> 2, q = rest & 3;
        int k0 = ks * 8 + q;
        const float* row = (n < 128) ? (W1 + n * 256) : (W1 + (n - 128) * 256 + 128);
        u32 v0 = cvt_tf32(row[k0]);
        u32 v1 = cvt_tf32(row[k0 + 4]);
        *(ull*)(smc + PC_WP + n * WP_STRIDE + ks * 32 + q * 8) = (ull)v0 | ((ull)v1 << 32);
    }
    // Stage x tile (clamped rows) into H layout, tf32
    for (int idx = tid; idx < 128 * 32; idx += 512) {
        int r = idx >> 5, c4 = idx & 31;
        int n = min(n0 + r, N - 1);
        float4 v = ((const float4*)x)[(size_t)n * 32 + c4];
        uint4 hv;
        hv.x = cvt_tf32(v.x); hv.y = cvt_tf32(v.y);
        hv.z = cvt_tf32(v.z); hv.w = cvt_tf32(v.w);
        *(uint4*)(smc + PC_X + r * H_STRIDE + c4 * 16) = hv;
    }
    __syncthreads();

    int wm = w & 3, wn = w >> 2;
    int lg = lane >> 2;               // 0..7
    int lq = lane & 3;                // 0..3

    u32 bOff = (u32)(PC_WP + (wn * 64 + lg) * WP_STRIDE + lq * 8);
    u32 aOff = (u32)(PC_X + (wm * 32 + lg) * H_STRIDE + lq * 4);

    float acc[2][8][4];
    #pragma unroll
    for (int mi = 0; mi < 2; mi++)
        #pragma unroll
        for (int ni = 0; ni < 8; ni++)
            #pragma unroll
            for (int qq = 0; qq < 4; qq++) acc[mi][ni][qq] = 0.0f;

    #pragma unroll
    for (int ks = 0; ks < 16; ks++) {
        u32 ko = (u32)(ks * 32);
        u32 bb[8][2];
        #pragma unroll
        for (int ni = 0; ni < 8; ni++) {
            ull v = *(const ull*)(smc + bOff + ni * 8 * WP_STRIDE + ko);
            bb[ni][0] = (u32)v; bb[ni][1] = (u32)(v >> 32);
        }
        #pragma unroll
        for (int mi = 0; mi < 2; mi++) {
            u32 ab = aOff + mi * 16 * H_STRIDE + ko;
            u32 a0 = *(const u32*)(smc + ab);
            u32 a2 = *(const u32*)(smc + ab + 16);
            u32 a1 = *(const u32*)(smc + ab + 8 * H_STRIDE);
            u32 a3 = *(const u32*)(smc + ab + 8 * H_STRIDE + 16);
            #pragma unroll
            for (int ni = 0; ni < 8; ni++)
                mma_tf32(acc[mi][ni], a0, a1, a2, a3, bb[ni][0], bb[ni][1]);
        }
    }

    // Epilogue: write fp32 to g_A (wn<2) / g_B (wn>=2)
    float* dst = (wn < 2) ? g_A : g_B;
    int jbase = (wn & 1) * 64;
    #pragma unroll
    for (int mi = 0; mi < 2; mi++) {
        int r0 = wm * 32 + mi * 16 + lg;
        #pragma unroll
        for (int ni = 0; ni < 8; ni++) {
            int j = jbase + ni * 8 + lq * 2;
            int n_a = n0 + r0, n_b = n0 + r0 + 8;
            if (n_a < N) *(float2*)&dst[(size_t)n_a * C + j] = make_float2(acc[mi][ni][0], acc[mi][ni][1]);
            if (n_b < N) *(float2*)&dst[(size_t)n_b * C + j] = make_float2(acc[mi][ni][2], acc[mi][ni][3]);
        }
    }
}

// ---------------------------------------------------------------------------
// Kernel 2: warp-specialized pipelined edge MLP, TF32 (round-10 proven).
// ---------------------------------------------------------------------------
#define H_TILE    (ET * H_STRIDE)          // 67584
#define OFF_WP    0                        // 69632
#define OFF_H     69632                    // + 2*67584 = 204800
#define OFF_B1    204800
#define OFF_B2    205312
#define OFF_W3    205824
#define OFF_PART  206336                   // 2 parity x 128 f32
#define OFF_B3    208384
#define ED_SMEM   208512

#define NTILES(E) (((E) + ET - 1) / ET)

__global__ void __launch_bounds__(512, 1)
edge_kernel(const void* __restrict__ ei,
            const float* __restrict__ W2, const float* __restrict__ b1,
            const float* __restrict__ b2, const float* __restrict__ W3,
            const float* __restrict__ b3, float* __restrict__ out, int E)
{
    extern __shared__ __align__(128) char smc[];
    u32 sb = smem_u32(smc);
    float* b1s = (float*)(smc + OFF_B1);
    float* b2s = (float*)(smc + OFF_B2);
    float* w3s = (float*)(smc + OFF_W3);
    float* part = (float*)(smc + OFF_PART);

    int tid = threadIdx.x;
    int lane = tid & 31, w = tid >> 5;
    bool i64 = idx_is_i64(ei);

    if (tid < 128) { b1s[tid] = b1[tid]; b2s[tid] = b2[tid]; w3s[tid] = W3[tid]; }
    if (tid == 0) *(float*)(smc + OFF_B3) = b3[0];
    // Stage W2 into paired tf32 layout (rna): slot (n, ks, q) <- (W[n][8ks+q], W[n][8ks+q+4])
    for (int idx = tid; idx < 128 * 64; idx += 512) {
        int n = idx >> 6, rest = idx & 63;
        int ks = rest >> 2, q = rest & 3;
        u32 v0 = cvt_tf32(W2[n * 128 + ks * 8 + q]);
        u32 v1 = cvt_tf32(W2[n * 128 + ks * 8 + q + 4]);
        *(ull*)(smc + OFF_WP + n * WP_STRIDE + ks * 32 + q * 8) = (ull)v0 | ((ull)v1 << 32);
    }
    __syncthreads();

    int ntiles = NTILES(E);

    if (w < 8) {
        // ========== PRODUCERS (256 thr): prefetch-pipelined line-coalesced gather ==========
        int el0 = w * 16;                  // 16 edges per producer warp
        int r = lane >> 3;                 // edge-in-group 0..3
        int q = lane & 7;                  // float4 index within 128B line
        const float4* b1v = (const float4*)b1s;
        int i = 0;
        for (int t = blockIdx.x; t < ntiles; t += EDGE_GRID, i++) {
            int b = i & 1;
            int myidx;
            {
                int ee = min(t * ET + el0 + (lane & 15), E - 1);
                if (i64) {
                    const long long* qq = (const long long*)ei;
                    myidx = (int)((lane < 16) ? qq[ee] : qq[(size_t)E + ee]);
                } else {
                    const int* qq = (const int*)ei;
                    myidx = (lane < 16) ? qq[ee] : qq[(size_t)E + ee];
                }
            }
            // Prefetch gg=0 gathers into registers BEFORE the buffer-free wait
            float4 av[4], bv[4];
            {
                int s  = __shfl_sync(0xFFFFFFFFu, myidx, r);
                int tg = __shfl_sync(0xFFFFFFFFu, myidx, 16 + r);
                const float4* Ar = (const float4*)g_A + (size_t)s  * 32 + q;
                const float4* Br = (const float4*)g_B + (size_t)tg * 32 + q;
                #pragma unroll
                for (int p = 0; p < 4; p++) { av[p] = Ar[8 * p]; bv[p] = Br[8 * p]; }
            }
            if (i >= NBUF) BAR_SYNC(3 + b, 512);
            #pragma unroll
            for (int gg = 0; gg < 4; gg++) {
                float4 nav[4], nbv[4];
                if (gg < 3) {
                    int jn = (gg + 1) * 4 + r;
                    int s  = __shfl_sync(0xFFFFFFFFu, myidx, jn);
                    int tg = __shfl_sync(0xFFFFFFFFu, myidx, 16 + jn);
                    const float4* Ar = (const float4*)g_A + (size_t)s  * 32 + q;
                    const float4* Br = (const float4*)g_B + (size_t)tg * 32 + q;
                    #pragma unroll
                    for (int p = 0; p < 4; p++) { nav[p] = Ar[8 * p]; nbv[p] = Br[8 * p]; }
                }
                int j = gg * 4 + r;
                char* hh = smc + OFF_H + b * H_TILE + (el0 + j) * H_STRIDE + q * 16;
                #pragma unroll
                for (int p = 0; p < 4; p++) {
                    float4 bi = b1v[q + 8 * p];
                    uint4 hv;
                    hv.x = cvt_tf32(elu_fast(av[p].x + bv[p].x + bi.x));
                    hv.y = cvt_tf32(elu_fast(av[p].y + bv[p].y + bi.y));
                    hv.z = cvt_tf32(elu_fast(av[p].z + bv[p].z + bi.z));
                    hv.w = cvt_tf32(elu_fast(av[p].w + bv[p].w + bi.w));
                    *(uint4*)(hh + p * 128) = hv;
                }
                if (gg < 3) {
                    #pragma unroll
                    for (int p = 0; p < 4; p++) { av[p] = nav[p]; bv[p] = nbv[p]; }
                }
            }
            MEMBAR_CTA();
            BAR_ARRIVE(1 + b, 512);
        }
    } else {
        // ========== CONSUMERS (256 thr): single-pass tf32 + pairwise epilogue ==========
        int cw = w - 8;
        int wm = cw & 3;                  // row block [wm*32,+32)
        int wh = cw >> 2;                 // col half  [wh*64,+64)
        int lg = lane >> 2;               // group id 0..7
        int lq = lane & 3;                // thread-in-group

        u32 bBase = sb + OFF_WP + (wh * 64 + lg) * WP_STRIDE + lq * 8;

        float b3v = *(float*)(smc + OFF_B3);
        int i = 0;
        for (int t = blockIdx.x; t < ntiles; t += EDGE_GRID, i++) {
            int b = i & 1;

            float acc[2][8][4];
            #pragma unroll
            for (int mi = 0; mi < 2; mi++)
                #pragma unroll
                for (int ni = 0; ni < 8; ni++)
                    #pragma unroll
                    for (int qq = 0; qq < 4; qq++) acc[mi][ni][qq] = 0.0f;

            u32 aBase = sb + OFF_H + b * H_TILE + (wm * 32 + lg) * H_STRIDE + lq * 4;

            BAR_SYNC(1 + b, 512);

            #pragma unroll
            for (int ks = 0; ks < 16; ks++) {
                u32 ko = (u32)(ks * 32);
                u32 bb[8][2];
                #pragma unroll
                for (int ni = 0; ni < 8; ni++) {
                    ull v = *(const ull*)(smc + (bBase - sb) + ni * 8 * WP_STRIDE + ko);
                    bb[ni][0] = (u32)v; bb[ni][1] = (u32)(v >> 32);
                }
                #pragma unroll
                for (int mi = 0; mi < 2; mi++) {
                    u32 ab = aBase - sb + mi * 16 * H_STRIDE + ko;
                    u32 a0 = *(const u32*)(smc + ab);
                    u32 a2 = *(const u32*)(smc + ab + 16);
                    u32 a1 = *(const u32*)(smc + ab + 8 * H_STRIDE);
                    u32 a3 = *(const u32*)(smc + ab + 8 * H_STRIDE + 16);
                    #pragma unroll
                    for (int ni = 0; ni < 8; ni++)
                        mma_tf32(acc[mi][ni], a0, a1, a2, a3, bb[ni][0], bb[ni][1]);
                }
            }
            BAR_ARRIVE(3 + b, 512);        // buffer free; epilogue in regs only

            // Per-row partials: pr[mi][half] on lanes lq==0
            float pr[2][2];
            #pragma unroll
            for (int mi = 0; mi < 2; mi++) {
                float p0 = 0.0f, p1 = 0.0f;
                #pragma unroll
                for (int ni = 0; ni < 8; ni++) {
                    int j = wh * 64 + ni * 8 + lq * 2;
                    float w3a = w3s[j], w3b = w3s[j + 1];
                    float b2a = b2s[j], b2b = b2s[j + 1];
                    p0 = fmaf(w3a, elu_fast(acc[mi][ni][0] + b2a), p0);
                    p0 = fmaf(w3b, elu_fast(acc[mi][ni][1] + b2b), p0);
                    p1 = fmaf(w3a, elu_fast(acc[mi][ni][2] + b2a), p1);
                    p1 = fmaf(w3b, elu_fast(acc[mi][ni][3] + b2b), p1);
                }
                p0 += __shfl_xor_sync(0xFFFFFFFFu, p0, 1);
                p0 += __shfl_xor_sync(0xFFFFFFFFu, p0, 2);
                p1 += __shfl_xor_sync(0xFFFFFFFFu, p1, 1);
                p1 += __shfl_xor_sync(0xFFFFFFFFu, p1, 2);
                pr[mi][0] = p0; pr[mi][1] = p1;
            }

            int par = i & 1;
            float* pp = part + par * 128;
            if (wh == 1) {
                if (lq == 0) {
                    #pragma unroll
                    for (int mi = 0; mi < 2; mi++) {
                        int rr = wm * 32 + mi * 16 + lg;
                        pp[rr]     = pr[mi][0];
                        pp[rr + 8] = pr[mi][1];
                    }
                }
                BAR_SYNC(6 + wm, 64);      // pair with wh==0 warp of same wm
            } else {
                BAR_SYNC(6 + wm, 64);
                if (lq == 0) {
                    #pragma unroll
                    for (int mi = 0; mi < 2; mi++) {
                        #pragma unroll
                        for (int hf = 0; hf < 2; hf++) {
                            int rr = wm * 32 + mi * 16 + lg + hf * 8;
                            int e = t * ET + rr;
                            if (e < E) out[e] = pr[mi][hf] + pp[rr] + b3v;
                        }
                    }
                }
            }
        }
    }
}

// ---------------------------------------------------------------------------
extern "C" void kernel_launch(void* const* d_in, const int* in_sizes, int n_in,
                              void* d_out, int out_size)
{
    const float* x  = (const float*)d_in[0];
    const void*  ei = d_in[1];
    const float* W1 = (const float*)d_in[2];
    const float* b1 = (const float*)d_in[3];
    const float* W2 = (const float*)d_in[4];
    const float* b2 = (const float*)d_in[5];
    const float* W3 = (const float*)d_in[6];
    const float* b3 = (const float*)d_in[7];
    float* out = (float*)d_out;

    int N = in_sizes[0] / C;        // 50000
    int E = in_sizes[1] / 2;        // 640000

    cudaFuncSetAttribute(precompute_mma_kernel, cudaFuncAttributeMaxDynamicSharedMemorySize, PC_SMEM);
    cudaFuncSetAttribute(edge_kernel,           cudaFuncAttributeMaxDynamicSharedMemorySize, ED_SMEM);

    precompute_mma_kernel<<<(N + 127) / 128, 512, PC_SMEM>>>(x, W1, N);
    edge_kernel<<<EDGE_GRID, 512, ED_SMEM>>>(ei, W2, b1, b2, W3, b3, out, E);
}